// round 3
// baseline (speedup 1.0000x reference)
#include <cuda_runtime.h>
#include <cuda_bf16.h>
#include <cstdint>

// Problem constants
#define Bb 4
#define Cc 3
#define Hh 1024
#define Ww 1024
#define NN (Hh * Ww)          // 2^20 pixels per image plane

// Padded warped scratch: [2 (flowset)][B][N][4 channels (3 used + 1 pad)]
// 2*4*2^20*4 floats = 128 MB. Device global (no dynamic allocation allowed).
__device__ float g_warp[(size_t)2 * Bb * NN * 4];
__device__ double g_acc;

// ---------------------------------------------------------------------------
// Vector reduction atomic: one 16B red.v4 instead of 3 scalar atomics.
// ---------------------------------------------------------------------------
__device__ __forceinline__ void red_add_v4(float* addr, float a, float b, float c) {
    asm volatile("red.global.add.v4.f32 [%0], {%1, %2, %3, %4};"
                 :: "l"(addr), "f"(a), "f"(b), "f"(c), "f"(0.0f)
                 : "memory");
}

// ---------------------------------------------------------------------------
// Kernel 1: zero the scratch (float4 stores) + the scalar accumulator.
// ---------------------------------------------------------------------------
__global__ void __launch_bounds__(256) zero_kernel() {
    const size_t n4 = (size_t)2 * Bb * NN;   // number of float4 groups (8.39M)
    size_t i = (size_t)blockIdx.x * 256u + threadIdx.x;
    float4* p = reinterpret_cast<float4*>(g_warp);
    if (i < n4) p[i] = make_float4(0.f, 0.f, 0.f, 0.f);
    if (i == 0) g_acc = 0.0;
}

// ---------------------------------------------------------------------------
// Kernel 2: bilinear forward splat. One thread per (flowset, batch, pixel).
//   flowset 0: im0 scattered with flow[0] * (1/t)
//   flowset 1: im1 scattered with flow[1] * (1/(1-t))
// ---------------------------------------------------------------------------
__global__ void __launch_bounds__(256) splat_kernel(
    const float* __restrict__ flows,   // [2, B, 2, H, W]
    const float* __restrict__ im0,     // [B, C, H, W]
    const float* __restrict__ im1,     // [B, C, H, W]
    const float* __restrict__ tv)      // [B]
{
    unsigned idx = blockIdx.x * 256u + threadIdx.x;
    if (idx >= 2u * Bb * NN) return;

    const unsigned f   = idx >> 22;                // B*N = 2^22
    const unsigned rem = idx & ((1u << 22) - 1u);
    const unsigned b   = rem >> 20;                // N = 2^20
    const unsigned p   = rem & (NN - 1u);
    const unsigned y   = p >> 10;
    const unsigned x   = p & 1023u;

    const float t = __ldg(&tv[b]);
    const float s = f ? (1.0f / (1.0f - t)) : (1.0f / t);

    const float* fl = flows + ((size_t)(f * Bb + b) * 2u) * NN;
    const float X = (float)x + s * __ldg(&fl[p]);
    const float Y = (float)y + s * __ldg(&fl[NN + p]);

    const float x0f = floorf(X), y0f = floorf(Y);
    const float fx = X - x0f,    fy = Y - y0f;
    const int   x0 = (int)x0f,   y0 = (int)y0f;

    const float* im = (f ? im1 : im0) + (size_t)b * (Cc * NN) + p;
    const float c0 = __ldg(&im[0]);
    const float c1 = __ldg(&im[NN]);
    const float c2 = __ldg(&im[2 * NN]);

    float* wbase = g_warp + (size_t)(f * Bb + b) * NN * 4u;

    const float wx0 = 1.0f - fx, wx1 = fx;
    const float wy0 = 1.0f - fy, wy1 = fy;
    const bool vx0 = (unsigned)x0       < (unsigned)Ww;
    const bool vx1 = (unsigned)(x0 + 1) < (unsigned)Ww;
    const bool vy0 = (unsigned)y0       < (unsigned)Hh;
    const bool vy1 = (unsigned)(y0 + 1) < (unsigned)Hh;

    if (vy0) {
        float* row = wbase + (size_t)y0 * (Ww * 4u);
        if (vx0) { const float w = wx0 * wy0; red_add_v4(row + 4 * x0,       w * c0, w * c1, w * c2); }
        if (vx1) { const float w = wx1 * wy0; red_add_v4(row + 4 * (x0 + 1), w * c0, w * c1, w * c2); }
    }
    if (vy1) {
        float* row = wbase + (size_t)(y0 + 1) * (Ww * 4u);
        if (vx0) { const float w = wx0 * wy1; red_add_v4(row + 4 * x0,       w * c0, w * c1, w * c2); }
        if (vx1) { const float w = wx1 * wy1; red_add_v4(row + 4 * (x0 + 1), w * c0, w * c1, w * c2); }
    }
}

// ---------------------------------------------------------------------------
// Kernel 3: L1 reduction. loss_sum = sum |warp_fir - im1| + sum |warp_sec - im0|
// Grid-stride over (b, p); float4 load per warped pixel group.
// ---------------------------------------------------------------------------
__global__ void __launch_bounds__(256) reduce_kernel(
    const float* __restrict__ im0,
    const float* __restrict__ im1)
{
    float acc = 0.0f;
    const unsigned total = Bb * NN;   // 4M
    for (unsigned i = blockIdx.x * 256u + threadIdx.x; i < total;
         i += gridDim.x * 256u) {
        const unsigned b = i >> 20;
        const unsigned p = i & (NN - 1u);

        const float4 wf = *reinterpret_cast<const float4*>(
            g_warp + (size_t)b * NN * 4u + (size_t)p * 4u);
        const float4 ws = *reinterpret_cast<const float4*>(
            g_warp + (size_t)(Bb + b) * NN * 4u + (size_t)p * 4u);

        const float* i0 = im0 + (size_t)b * (Cc * NN) + p;
        const float* i1 = im1 + (size_t)b * (Cc * NN) + p;

        acc += fabsf(wf.x - __ldg(&i1[0]))
             + fabsf(wf.y - __ldg(&i1[NN]))
             + fabsf(wf.z - __ldg(&i1[2 * NN]));
        acc += fabsf(ws.x - __ldg(&i0[0]))
             + fabsf(ws.y - __ldg(&i0[NN]))
             + fabsf(ws.z - __ldg(&i0[2 * NN]));
    }

    // warp reduce
    #pragma unroll
    for (int o = 16; o; o >>= 1) acc += __shfl_xor_sync(0xffffffffu, acc, o);

    __shared__ float ssum[8];
    if ((threadIdx.x & 31u) == 0u) ssum[threadIdx.x >> 5] = acc;
    __syncthreads();
    if (threadIdx.x < 8u) {
        float v = ssum[threadIdx.x];
        #pragma unroll
        for (int o = 4; o; o >>= 1) v += __shfl_xor_sync(0xffu, v, o);
        if (threadIdx.x == 0u) atomicAdd(&g_acc, (double)v);
    }
}

// ---------------------------------------------------------------------------
// Kernel 4: finalize. loss = (sum1 + sum2) / (B*C*H*W)  (same divisor for both means)
// ---------------------------------------------------------------------------
__global__ void finalize_kernel(float* __restrict__ out) {
    out[0] = (float)(g_acc / (double)((size_t)Bb * Cc * NN));
}

// ---------------------------------------------------------------------------
// Launch
// inputs (metadata order): flows [2,B,2,H,W], im0 [B,C,H,W], im1 [B,C,H,W], t [B]
// output: scalar float
// ---------------------------------------------------------------------------
extern "C" void kernel_launch(void* const* d_in, const int* in_sizes, int n_in,
                              void* d_out, int out_size) {
    const float* flows = (const float*)d_in[0];
    const float* im0   = (const float*)d_in[1];
    const float* im1   = (const float*)d_in[2];
    const float* tv    = (const float*)d_in[3];
    float* out = (float*)d_out;

    // zero: 2*B*N float4 groups = 8,388,608 threads
    {
        const unsigned n4 = 2u * Bb * NN;
        zero_kernel<<<(n4 + 255u) / 256u, 256>>>();
    }
    // splat: 2*B*N threads
    {
        const unsigned n = 2u * Bb * NN;
        splat_kernel<<<(n + 255u) / 256u, 256>>>(flows, im0, im1, tv);
    }
    // reduce: fixed grid, grid-stride
    reduce_kernel<<<2048, 256>>>(im0, im1);
    finalize_kernel<<<1, 1>>>(out);
}